// round 5
// baseline (speedup 1.0000x reference)
#include <cuda_runtime.h>
#include <math.h>
#include <stdint.h>

#define BB   64
#define NE   500
#define NR   500
#define C1   151
#define CM   150
#define NEP  512   // padded entity count
#define NRP  512   // padded relation count
#define TR   64
#define TE   128

// ---------------- packed f32x2 helpers (Blackwell) ----------------------------------
#define FMA_F32X2(d, a, b, c) \
  asm("fma.rn.f32x2 %0, %1, %2, %3;" : "=l"(d) : "l"(a), "l"(b), "l"(c))
#define PACK2(d, lo, hi) \
  asm("mov.b64 %0, {%1, %2};" : "=l"(d) : "f"(lo), "f"(hi))
#define UNPACK2(lo, hi, d) \
  asm("mov.b64 {%0, %1}, %2;" : "=f"(lo), "=f"(hi) : "l"(d))

// ---------------- scratch (device globals; zero-initialized, pads never written) ----
__device__ float  g_ent_prob_t[BB][CM][NEP];   // [b][k][e]
__device__ float  g_rs_prob_t [BB][CM][NRP];   // [b][k][r]
__device__ float  g_ro_prob_t [BB][CM][NRP];
__device__ float  g_ent_score [BB][NEP];
__device__ float  g_ent_sumsq [BB][NEP];
__device__ float4 g_ent_box   [BB][NEP];       // scaled xyxy
__device__ float2 g_ent_cnt   [BB][NEP];       // scaled centers
__device__ float  g_rs_sumsq  [BB][NRP];
__device__ float  g_ro_sumsq  [BB][NRP];
__device__ float4 g_rs_box    [BB][NRP];
__device__ float4 g_ro_box    [BB][NRP];
__device__ float4 g_rel_vec   [BB][NRP];

__device__ __forceinline__ float warp_max(float v){
  #pragma unroll
  for (int o = 16; o; o >>= 1) v = fmaxf(v, __shfl_xor_sync(0xffffffffu, v, o));
  return v;
}
__device__ __forceinline__ float warp_sum(float v){
  #pragma unroll
  for (int o = 16; o; o >>= 1) v += __shfl_xor_sync(0xffffffffu, v, o);
  return v;
}

// ---------------- Phase 1a: entity softmax (transposed store), score, sumsq, boxes --
__global__ void ent_kernel(const float* __restrict__ boxes,
                           const float* __restrict__ logits,
                           const float* __restrict__ tsizes)
{
  __shared__ float sp[32][CM + 3];   // pitch 153 -> conflict-free transpose
  int b   = blockIdx.y;
  int e0  = blockIdx.x * 32;
  int tid = threadIdx.x, warp = tid >> 5, lane = tid & 31;
  float H = tsizes[2*b + 0], W = tsizes[2*b + 1];

  #pragma unroll
  for (int i = 0; i < 4; i++){
    int el = warp*4 + i;
    int e  = e0 + el;
    if (e >= NE) continue;
    const float* row = logits + ((size_t)b*NE + e)*C1;
    float v[5]; float mx = -INFINITY, mx150 = -INFINITY;
    #pragma unroll
    for (int j = 0; j < 5; j++){
      int k = lane + 32*j;
      v[j] = (k < C1) ? row[k] : -INFINITY;
      mx = fmaxf(mx, v[j]);
      if (k < CM) mx150 = fmaxf(mx150, v[j]);
    }
    mx = warp_max(mx); mx150 = warp_max(mx150);
    float s = 0.f;
    #pragma unroll
    for (int j = 0; j < 5; j++){
      int k = lane + 32*j;
      float ev = (k < C1) ? __expf(v[j] - mx) : 0.f;
      v[j] = ev; s += ev;
    }
    s = warp_sum(s);
    float inv = __fdividef(1.f, s);
    float sq = 0.f;
    #pragma unroll
    for (int j = 0; j < 5; j++){
      int k = lane + 32*j;
      if (k < CM){ float p = v[j]*inv; sp[el][k] = p; sq += p*p; }
    }
    sq = warp_sum(sq);
    if (lane == 0){
      g_ent_score[b][e] = __expf(mx150 - mx) * inv;
      g_ent_sumsq[b][e] = sq;
      const float* bx = boxes + ((size_t)b*NE + e)*4;
      float cx = bx[0], cy = bx[1], w = bx[2], h = bx[3];
      float x0 = (cx - 0.5f*w)*W, y0 = (cy - 0.5f*h)*H;
      float x1 = (cx + 0.5f*w)*W, y1 = (cy + 0.5f*h)*H;
      g_ent_box[b][e] = make_float4(x0, y0, x1, y1);
      g_ent_cnt[b][e] = make_float2((x0 + x1)*0.5f, (y0 + y1)*0.5f);
    }
  }
  __syncthreads();
  for (int idx = tid; idx < CM*32; idx += blockDim.x){
    int el = idx & 31, k = idx >> 5;
    int e = e0 + el;
    if (e < NE) g_ent_prob_t[b][k][e] = sp[el][k];
  }
}

// ---------------- Phase 1b: relation softmaxes -> transposed store ------------------
__device__ __forceinline__ float rel_row(const float* __restrict__ row,
                                         float sp[32][CM + 3], int el, int lane)
{
  float v[5]; float mx = -INFINITY;
  #pragma unroll
  for (int j = 0; j < 5; j++){
    int k = lane + 32*j;
    v[j] = (k < C1) ? row[k] : -INFINITY;
    mx = fmaxf(mx, v[j]);
  }
  mx = warp_max(mx);
  float s = 0.f;
  #pragma unroll
  for (int j = 0; j < 5; j++){
    int k = lane + 32*j;
    float ev = (k < C1) ? __expf(v[j] - mx) : 0.f;
    v[j] = ev; s += ev;
  }
  s = warp_sum(s);
  float inv = __fdividef(1.f, s);
  float sq = 0.f;
  #pragma unroll
  for (int j = 0; j < 5; j++){
    int k = lane + 32*j;
    if (k < CM){ float p = v[j]*inv; sp[el][k] = p; sq += p*p; }
  }
  return warp_sum(sq);
}

__global__ void rel_kernel(const float* __restrict__ ro_logits,
                           const float* __restrict__ rs_logits,
                           const float* __restrict__ ro_box,
                           const float* __restrict__ rs_box,
                           const float* __restrict__ rel_vec,
                           const float* __restrict__ tsizes)
{
  __shared__ float sps[32][CM + 3];
  __shared__ float spo[32][CM + 3];
  int b   = blockIdx.y;
  int r0  = blockIdx.x * 32;
  int tid = threadIdx.x, warp = tid >> 5, lane = tid & 31;
  float H = tsizes[2*b + 0], W = tsizes[2*b + 1];
  #pragma unroll
  for (int i = 0; i < 4; i++){
    int el = warp*4 + i;
    int r = r0 + el;
    if (r >= NR) continue;
    size_t off = ((size_t)b*NR + r)*C1;
    float sq_s = rel_row(rs_logits + off, sps, el, lane);
    float sq_o = rel_row(ro_logits + off, spo, el, lane);
    if (lane == 0){
      g_rs_sumsq[b][r] = sq_s;
      g_ro_sumsq[b][r] = sq_o;
      const float* bs = rs_box + ((size_t)b*NR + r)*4;
      float cx = bs[0], cy = bs[1], w = bs[2], h = bs[3];
      g_rs_box[b][r] = make_float4((cx-0.5f*w)*W, (cy-0.5f*h)*H,
                                   (cx+0.5f*w)*W, (cy+0.5f*h)*H);
      const float* bo = ro_box + ((size_t)b*NR + r)*4;
      cx = bo[0]; cy = bo[1]; w = bo[2]; h = bo[3];
      g_ro_box[b][r] = make_float4((cx-0.5f*w)*W, (cy-0.5f*h)*H,
                                   (cx+0.5f*w)*W, (cy+0.5f*h)*H);
      const float* rv = rel_vec + ((size_t)b*NR + r)*4;
      g_rel_vec[b][r] = make_float4(rv[0]*W, rv[1]*H, rv[2]*W, rv[3]*H);
    }
  }
  __syncthreads();
  // transposed store: gmem coalesced along r, smem read conflict-free (153 % 32 = 25)
  for (int idx = tid; idx < CM*32; idx += blockDim.x){
    int el = idx & 31, k = idx >> 5;
    int r = r0 + el;
    if (r < NR){
      g_rs_prob_t[b][k][r] = sps[el][k];
      g_ro_prob_t[b][k][r] = spo[el][k];
    }
  }
}

// ---------------- Phase 2: pairwise tile kernel --------------------------------------
struct SmemP2 {
  float  entT[CM][TE];   // [k][e]  76.8 KB
  float  rsT [CM][TR];   // [k][r]  38.4 KB
  float  roT [CM][TR];   //          38.4 KB
  float4 ebox [TE];
  float2 ecnt [TE];
  float  escore[TE];
  float  esq  [TE];
  float4 rsbox[TR];
  float4 robox[TR];
  float4 rvec [TR];
  float  rssq [TR];
  float  rosq [TR];
};

__device__ __forceinline__ float giou2(float4 a, float areaA, float4 b, float areaB){
  float iw = fmaxf(fminf(a.z, b.z) - fmaxf(a.x, b.x), 0.f);
  float ih = fmaxf(fminf(a.w, b.w) - fmaxf(a.y, b.y), 0.f);
  float inter = iw * ih;
  float uni = areaA + areaB - inter;
  float cw = fmaxf(fmaxf(a.z, b.z) - fminf(a.x, b.x), 0.f);
  float ch = fmaxf(fmaxf(a.w, b.w) - fminf(a.y, b.y), 0.f);
  float areaC = cw * ch;
  float g = __fdividef(inter, uni) - __fdividef(areaC - uni, areaC);
  return fmaxf(g, 0.f);
}

__global__ void __launch_bounds__(512, 1) phase2_kernel(float* __restrict__ out_s,
                                                        float* __restrict__ out_o)
{
  extern __shared__ char smem_raw[];
  SmemP2& sm = *reinterpret_cast<SmemP2*>(smem_raw);
  int b  = blockIdx.z;
  int e0 = blockIdx.x * TE;
  int r0 = blockIdx.y * TR;
  int tid = threadIdx.x;

  // ---- tile loads (scratch padded to 512 -> no guards) ----
  if (tid < TE){
    int e = e0 + tid;
    sm.ebox[tid]   = g_ent_box[b][e];
    sm.ecnt[tid]   = g_ent_cnt[b][e];
    sm.escore[tid] = g_ent_score[b][e];
    sm.esq[tid]    = g_ent_sumsq[b][e];
  } else if (tid < TE + TR){
    int t = tid - TE;
    int r = r0 + t;
    sm.rsbox[t] = g_rs_box[b][r];
    sm.robox[t] = g_ro_box[b][r];
    sm.rvec[t]  = g_rel_vec[b][r];
    sm.rssq[t]  = g_rs_sumsq[b][r];
    sm.rosq[t]  = g_ro_sumsq[b][r];
  }
  // entT: 150 x 32 float4
  for (int idx = tid; idx < CM*(TE/4); idx += 512){
    int k = idx >> 5, q = idx & 31;
    *(float4*)&sm.entT[k][q*4] = *((const float4*)&g_ent_prob_t[b][k][e0] + q);
  }
  // rsT/roT: 150 x 16 float4 each
  for (int idx = tid; idx < CM*(TR/4); idx += 512){
    int k = idx >> 4, q = idx & 15;
    *(float4*)&sm.rsT[k][q*4] = *((const float4*)&g_rs_prob_t[b][k][r0] + q);
    *(float4*)&sm.roT[k][q*4] = *((const float4*)&g_ro_prob_t[b][k][r0] + q);
  }
  __syncthreads();

  int te = tid & 31, tr = tid >> 5;   // 32 e-groups x 16 r-groups
  int el = te * 4, rl = tr * 4;

  unsigned long long accS[2][4], accO[2][4];
  #pragma unroll
  for (int ip = 0; ip < 2; ip++)
    #pragma unroll
    for (int j = 0; j < 4; j++){ accS[ip][j] = 0ULL; accO[ip][j] = 0ULL; }

  const float* pe = &sm.entT[0][el];
  const float* ps = &sm.rsT[0][rl];
  const float* po = &sm.roT[0][rl];

  #pragma unroll 2
  for (int k = 0; k < CM; k++){
    float4 bv  = *(const float4*)pe;  pe += TE;
    float4 as4 = *(const float4*)ps;  ps += TR;
    float4 ao4 = *(const float4*)po;  po += TR;
    unsigned long long b0, b1, b2, b3, s01, s23, o01, o23;
    PACK2(b0, bv.x, bv.x);  PACK2(b1, bv.y, bv.y);
    PACK2(b2, bv.z, bv.z);  PACK2(b3, bv.w, bv.w);
    PACK2(s01, as4.x, as4.y); PACK2(s23, as4.z, as4.w);
    PACK2(o01, ao4.x, ao4.y); PACK2(o23, ao4.z, ao4.w);
    FMA_F32X2(accS[0][0], s01, b0, accS[0][0]);
    FMA_F32X2(accS[0][1], s01, b1, accS[0][1]);
    FMA_F32X2(accS[0][2], s01, b2, accS[0][2]);
    FMA_F32X2(accS[0][3], s01, b3, accS[0][3]);
    FMA_F32X2(accS[1][0], s23, b0, accS[1][0]);
    FMA_F32X2(accS[1][1], s23, b1, accS[1][1]);
    FMA_F32X2(accS[1][2], s23, b2, accS[1][2]);
    FMA_F32X2(accS[1][3], s23, b3, accS[1][3]);
    FMA_F32X2(accO[0][0], o01, b0, accO[0][0]);
    FMA_F32X2(accO[0][1], o01, b1, accO[0][1]);
    FMA_F32X2(accO[0][2], o01, b2, accO[0][2]);
    FMA_F32X2(accO[0][3], o01, b3, accO[0][3]);
    FMA_F32X2(accO[1][0], o23, b0, accO[1][0]);
    FMA_F32X2(accO[1][1], o23, b1, accO[1][1]);
    FMA_F32X2(accO[1][2], o23, b2, accO[1][2]);
    FMA_F32X2(accO[1][3], o23, b3, accO[1][3]);
  }

  // unpack: dot[i][j], i = r-offset, j = e-offset
  float dS[4][4], dO[4][4];
  #pragma unroll
  for (int ip = 0; ip < 2; ip++)
    #pragma unroll
    for (int j = 0; j < 4; j++){
      UNPACK2(dS[2*ip][j], dS[2*ip+1][j], accS[ip][j]);
      UNPACK2(dO[2*ip][j], dO[2*ip+1][j], accO[ip][j]);
    }

  // hoist per-e data
  float4 eb[4]; float2 ec[4]; float esc[4], esq[4], areaE[4];
  #pragma unroll
  for (int j = 0; j < 4; j++){
    eb[j]    = sm.ebox[el + j];
    ec[j]    = sm.ecnt[el + j];
    esc[j]   = sm.escore[el + j];
    esq[j]   = sm.esq[el + j];
    areaE[j] = (eb[j].z - eb[j].x)*(eb[j].w - eb[j].y);
  }

  #pragma unroll
  for (int i = 0; i < 4; i++){
    int r = r0 + rl + i;
    if (r >= NR) continue;
    float4 rsb = sm.rsbox[rl + i];
    float4 rob = sm.robox[rl + i];
    float4 rv  = sm.rvec[rl + i];
    float  sqs = sm.rssq[rl + i];
    float  sqo = sm.rosq[rl + i];
    float areaRS = (rsb.z - rsb.x)*(rsb.w - rsb.y);
    float areaRO = (rob.z - rob.x)*(rob.w - rob.y);
    float resS[4], resO[4];
    #pragma unroll
    for (int j = 0; j < 4; j++){
      // subject
      float ds  = fabsf(rv.x - ec[j].x) + fabsf(rv.y - ec[j].y);
      float ms  = esc[j] * __fdividef(1.f, ds + 1.f);
      float d2  = sqs + esq[j] - 2.f*dS[i][j];
      float cd  = sqrtf(fmaxf(d2, 1e-12f));
      float cls = __fdividef(1.f, cd + 1.f);
      resS[j] = ms * cls * giou2(eb[j], areaE[j], rsb, areaRS);
      // object
      float dd   = fabsf(rv.z - ec[j].x) + fabsf(rv.w - ec[j].y);
      float mo   = esc[j] * __fdividef(1.f, dd + 1.f);
      float d2o  = sqo + esq[j] - 2.f*dO[i][j];
      float cdo  = sqrtf(fmaxf(d2o, 1e-12f));
      float clso = __fdividef(1.f, cdo + 1.f);
      resO[j] = mo * clso * giou2(eb[j], areaE[j], rob, areaRO);
    }
    size_t base = ((size_t)b*NR + r)*NE + (size_t)(e0 + el);
    if (e0 + el + 3 < NE){
      *(float4*)(out_s + base) = make_float4(resS[0], resS[1], resS[2], resS[3]);
      *(float4*)(out_o + base) = make_float4(resO[0], resO[1], resO[2], resO[3]);
    } else {
      #pragma unroll
      for (int j = 0; j < 4; j++){
        if (e0 + el + j < NE){ out_s[base + j] = resS[j]; out_o[base + j] = resO[j]; }
      }
    }
  }
}

// ---------------- launch --------------------------------------------------------------
extern "C" void kernel_launch(void* const* d_in, const int* in_sizes, int n_in,
                              void* d_out, int out_size)
{
  const float* pred_boxes  = (const float*)d_in[0];
  const float* pred_logits = (const float*)d_in[1];
  const float* ro_logits   = (const float*)d_in[2];
  const float* rs_logits   = (const float*)d_in[3];
  const float* ro_box      = (const float*)d_in[4];
  const float* rs_box      = (const float*)d_in[5];
  const float* rel_vec     = (const float*)d_in[6];
  const float* tsizes      = (const float*)d_in[7];
  float* out_s = (float*)d_out;
  float* out_o = out_s + (size_t)BB*NR*NE;

  static bool attr_set = false;
  if (!attr_set){
    cudaFuncSetAttribute(phase2_kernel, cudaFuncAttributeMaxDynamicSharedMemorySize,
                         (int)sizeof(SmemP2));
    attr_set = true;
  }

  dim3 g1((NE + 31) / 32, BB);
  ent_kernel<<<g1, 256>>>(pred_boxes, pred_logits, tsizes);
  dim3 g2((NR + 31) / 32, BB);
  rel_kernel<<<g2, 256>>>(ro_logits, rs_logits, ro_box, rs_box, rel_vec, tsizes);
  dim3 g3((NEP + TE - 1) / TE, (NRP + TR - 1) / TR, BB);
  phase2_kernel<<<g3, 512, sizeof(SmemP2)>>>(out_s, out_o);
}

// round 6
// speedup vs baseline: 1.6938x; 1.6938x over previous
#include <cuda_runtime.h>
#include <cuda_bf16.h>
#include <math.h>
#include <stdint.h>

#define BB   64
#define NE   500
#define NR   500
#define C1   151
#define CM   150
#define NEP  512
#define NRP  512
#define KP   480    // split-K: [0,150)=hi, [150,300)=mix, [300,450)=lo-part, [450,480)=0
#define KC   80     // k-chunk (bf16 elements)
#define NCH  6      // KP / KC
#define SP   88     // smem pitch (bf16) -> 176B rows, conflict-free for ldmatrix
#define SPB  176
#define TE   128
#define TR   128
#define BUFB (128*SPB)

// ---------------- scratch (device globals; zero-init, pads never written) -----------
__device__ __nv_bfloat16 g_entB[BB][NEP][KP];  // B': [bh | bl | bh | 0]
__device__ __nv_bfloat16 g_rsA [BB][NRP][KP];  // A': [ah | ah | al | 0]
__device__ __nv_bfloat16 g_roA [BB][NRP][KP];
__device__ float  g_ent_score [BB][NEP];
__device__ float  g_ent_sumsq [BB][NEP];
__device__ float4 g_ent_box   [BB][NEP];
__device__ float2 g_ent_cnt   [BB][NEP];
__device__ float  g_rs_sumsq  [BB][NRP];
__device__ float  g_ro_sumsq  [BB][NRP];
__device__ float4 g_rs_box    [BB][NRP];
__device__ float4 g_ro_box    [BB][NRP];
__device__ float4 g_rel_vec   [BB][NRP];

// ---------------- small helpers ------------------------------------------------------
__device__ __forceinline__ float warp_max(float v){
  #pragma unroll
  for (int o = 16; o; o >>= 1) v = fmaxf(v, __shfl_xor_sync(0xffffffffu, v, o));
  return v;
}
__device__ __forceinline__ float warp_sum(float v){
  #pragma unroll
  for (int o = 16; o; o >>= 1) v += __shfl_xor_sync(0xffffffffu, v, o);
  return v;
}
__device__ __forceinline__ uint32_t s2u(const void* p){
  uint32_t a;
  asm("{ .reg .u64 t; cvta.to.shared.u64 t, %1; cvt.u32.u64 %0, t; }" : "=r"(a) : "l"(p));
  return a;
}
__device__ __forceinline__ void ldsm_x4(uint32_t* r, uint32_t addr){
  asm volatile("ldmatrix.sync.aligned.m8n8.x4.shared.b16 {%0,%1,%2,%3}, [%4];"
    : "=r"(r[0]), "=r"(r[1]), "=r"(r[2]), "=r"(r[3]) : "r"(addr));
}
__device__ __forceinline__ void mma16816(float* d, const uint32_t* a, uint32_t b0, uint32_t b1){
  asm volatile("mma.sync.aligned.m16n8k16.row.col.f32.bf16.bf16.f32 "
    "{%0,%1,%2,%3}, {%4,%5,%6,%7}, {%8,%9}, {%0,%1,%2,%3};"
    : "+f"(d[0]), "+f"(d[1]), "+f"(d[2]), "+f"(d[3])
    : "r"(a[0]), "r"(a[1]), "r"(a[2]), "r"(a[3]), "r"(b0), "r"(b1));
}
__device__ __forceinline__ void cp16(uint32_t dst, const void* src){
  asm volatile("cp.async.cg.shared.global [%0], [%1], 16;" :: "r"(dst), "l"(src));
}
__device__ __forceinline__ void cp_commit(){ asm volatile("cp.async.commit_group;"); }
template<int N> __device__ __forceinline__ void cp_wait(){
  asm volatile("cp.async.wait_group %0;" :: "n"(N));
}

// ---------------- Phase 1a: entity softmax -> split-bf16 B' rows ---------------------
__global__ void ent_kernel(const float* __restrict__ boxes,
                           const float* __restrict__ logits,
                           const float* __restrict__ tsizes)
{
  int b   = blockIdx.y;
  int e0  = blockIdx.x * 32;
  int tid = threadIdx.x, warp = tid >> 5, lane = tid & 31;
  float H = tsizes[2*b + 0], W = tsizes[2*b + 1];

  #pragma unroll
  for (int i = 0; i < 4; i++){
    int e = e0 + warp*4 + i;
    if (e >= NE) continue;
    const float* row = logits + ((size_t)b*NE + e)*C1;
    float v[5]; float mx = -INFINITY, mx150 = -INFINITY;
    #pragma unroll
    for (int j = 0; j < 5; j++){
      int k = lane + 32*j;
      v[j] = (k < C1) ? row[k] : -INFINITY;
      mx = fmaxf(mx, v[j]);
      if (k < CM) mx150 = fmaxf(mx150, v[j]);
    }
    mx = warp_max(mx); mx150 = warp_max(mx150);
    float s = 0.f;
    #pragma unroll
    for (int j = 0; j < 5; j++){
      int k = lane + 32*j;
      float ev = (k < C1) ? __expf(v[j] - mx) : 0.f;
      v[j] = ev; s += ev;
    }
    s = warp_sum(s);
    float inv = __fdividef(1.f, s);
    float sq = 0.f;
    __nv_bfloat16* dst = &g_entB[b][e][0];
    #pragma unroll
    for (int j = 0; j < 5; j++){
      int k = lane + 32*j;
      if (k < CM){
        float p = v[j]*inv; sq += p*p;
        __nv_bfloat16 ph = __float2bfloat16(p);
        __nv_bfloat16 pl = __float2bfloat16(p - __bfloat162float(ph));
        dst[k] = ph; dst[CM + k] = pl; dst[2*CM + k] = ph;
      }
    }
    sq = warp_sum(sq);
    if (lane == 0){
      g_ent_score[b][e] = __expf(mx150 - mx) * inv;
      g_ent_sumsq[b][e] = sq;
      const float* bx = boxes + ((size_t)b*NE + e)*4;
      float cx = bx[0], cy = bx[1], w = bx[2], h = bx[3];
      float x0 = (cx - 0.5f*w)*W, y0 = (cy - 0.5f*h)*H;
      float x1 = (cx + 0.5f*w)*W, y1 = (cy + 0.5f*h)*H;
      g_ent_box[b][e] = make_float4(x0, y0, x1, y1);
      g_ent_cnt[b][e] = make_float2((x0 + x1)*0.5f, (y0 + y1)*0.5f);
    }
  }
}

// ---------------- Phase 1b: relation softmaxes -> split-bf16 A' rows ------------------
__device__ __forceinline__ float rel_row(const float* __restrict__ row,
                                         __nv_bfloat16* __restrict__ dst, int lane)
{
  float v[5]; float mx = -INFINITY;
  #pragma unroll
  for (int j = 0; j < 5; j++){
    int k = lane + 32*j;
    v[j] = (k < C1) ? row[k] : -INFINITY;
    mx = fmaxf(mx, v[j]);
  }
  mx = warp_max(mx);
  float s = 0.f;
  #pragma unroll
  for (int j = 0; j < 5; j++){
    int k = lane + 32*j;
    float ev = (k < C1) ? __expf(v[j] - mx) : 0.f;
    v[j] = ev; s += ev;
  }
  s = warp_sum(s);
  float inv = __fdividef(1.f, s);
  float sq = 0.f;
  #pragma unroll
  for (int j = 0; j < 5; j++){
    int k = lane + 32*j;
    if (k < CM){
      float p = v[j]*inv; sq += p*p;
      __nv_bfloat16 ah = __float2bfloat16(p);
      __nv_bfloat16 al = __float2bfloat16(p - __bfloat162float(ah));
      dst[k] = ah; dst[CM + k] = ah; dst[2*CM + k] = al;
    }
  }
  return warp_sum(sq);
}

__global__ void rel_kernel(const float* __restrict__ ro_logits,
                           const float* __restrict__ rs_logits,
                           const float* __restrict__ ro_box,
                           const float* __restrict__ rs_box,
                           const float* __restrict__ rel_vec,
                           const float* __restrict__ tsizes)
{
  int b   = blockIdx.y;
  int r0  = blockIdx.x * 32;
  int tid = threadIdx.x, warp = tid >> 5, lane = tid & 31;
  float H = tsizes[2*b + 0], W = tsizes[2*b + 1];
  #pragma unroll
  for (int i = 0; i < 4; i++){
    int r = r0 + warp*4 + i;
    if (r >= NR) continue;
    size_t off = ((size_t)b*NR + r)*C1;
    float sq_s = rel_row(rs_logits + off, &g_rsA[b][r][0], lane);
    float sq_o = rel_row(ro_logits + off, &g_roA[b][r][0], lane);
    if (lane == 0){
      g_rs_sumsq[b][r] = sq_s;
      g_ro_sumsq[b][r] = sq_o;
      const float* bs = rs_box + ((size_t)b*NR + r)*4;
      float cx = bs[0], cy = bs[1], w = bs[2], h = bs[3];
      g_rs_box[b][r] = make_float4((cx-0.5f*w)*W, (cy-0.5f*h)*H,
                                   (cx+0.5f*w)*W, (cy+0.5f*h)*H);
      const float* bo = ro_box + ((size_t)b*NR + r)*4;
      cx = bo[0]; cy = bo[1]; w = bo[2]; h = bo[3];
      g_ro_box[b][r] = make_float4((cx-0.5f*w)*W, (cy-0.5f*h)*H,
                                   (cx+0.5f*w)*W, (cy+0.5f*h)*H);
      const float* rv = rel_vec + ((size_t)b*NR + r)*4;
      g_rel_vec[b][r] = make_float4(rv[0]*W, rv[1]*H, rv[2]*W, rv[3]*H);
    }
  }
}

// ---------------- Phase 2: tensor-core GEMM + fused epilogue -------------------------
struct SmemP2 {
  __nv_bfloat16 rs [2][128][SP];
  __nv_bfloat16 ro [2][128][SP];
  __nv_bfloat16 ent[2][128][SP];
  float4 ebox [TE];
  float2 ecnt [TE];
  float  escore[TE];
  float  esq  [TE];
  float4 rsbox[TR];
  float4 robox[TR];
  float4 rvec [TR];
  float  rssq [TR];
  float  rosq [TR];
};

__device__ __forceinline__ float giou1(float4 a, float areaA, float4 b, float areaB){
  float iw = fmaxf(fminf(a.z, b.z) - fmaxf(a.x, b.x), 0.f);
  float ih = fmaxf(fminf(a.w, b.w) - fmaxf(a.y, b.y), 0.f);
  float inter = iw * ih;
  float uni = areaA + areaB - inter;
  float cw = fmaxf(fmaxf(a.z, b.z) - fminf(a.x, b.x), 0.f);
  float ch = fmaxf(fmaxf(a.w, b.w) - fminf(a.y, b.y), 0.f);
  float areaC = cw * ch;
  // inter/uni + uni/areaC - 1, single reciprocal
  float invden = __fdividef(1.f, uni * areaC);
  float g = (inter*areaC + uni*(uni - areaC)) * invden;
  return fmaxf(g, 0.f);
}

__device__ __forceinline__ void load_chunk(uint32_t rsS, uint32_t roS, uint32_t entS,
                                           const __nv_bfloat16* grs,
                                           const __nv_bfloat16* gro,
                                           const __nv_bfloat16* gent,
                                           int buf, int c, int tid)
{
  uint32_t bufo = buf * BUFB;
  #pragma unroll
  for (int it = 0; it < 8; it++){
    int idx = tid + it*512;
    if (idx >= 3840) break;
    int m   = idx / 1280;
    int rem = idx - m*1280;
    int row = rem / 10;
    int c16 = rem - row*10;
    uint32_t soff = bufo + row*SPB + c16*16;
    size_t   goff = (size_t)row*KP + (size_t)c*KC + c16*8;
    if      (m == 0) cp16(rsS  + soff, grs  + goff);
    else if (m == 1) cp16(roS  + soff, gro  + goff);
    else             cp16(entS + soff, gent + goff);
  }
}

__global__ void __launch_bounds__(512, 1) phase2_kernel(float* __restrict__ out_s,
                                                        float* __restrict__ out_o)
{
  extern __shared__ char smem_raw[];
  SmemP2& sm = *reinterpret_cast<SmemP2*>(smem_raw);
  int b  = blockIdx.z;
  int e0 = blockIdx.x * TE;
  int r0 = blockIdx.y * TR;
  int tid = threadIdx.x;
  int lane = tid & 31, wid = tid >> 5;
  int wr = wid >> 2, we = wid & 3;          // 4x4 warp grid
  int rbase = wr * 32, ebase = we * 32;

  const __nv_bfloat16* grs  = &g_rsA [b][r0][0];
  const __nv_bfloat16* gro  = &g_roA [b][r0][0];
  const __nv_bfloat16* gent = &g_entB[b][e0][0];
  uint32_t rsS  = s2u(&sm.rs [0][0][0]);
  uint32_t roS  = s2u(&sm.ro [0][0][0]);
  uint32_t entS = s2u(&sm.ent[0][0][0]);

  // epilogue scalar tiles (visible after first __syncthreads)
  if (tid < TE){
    int e = e0 + tid;
    sm.ebox[tid]   = g_ent_box[b][e];
    sm.ecnt[tid]   = g_ent_cnt[b][e];
    sm.escore[tid] = g_ent_score[b][e];
    sm.esq[tid]    = g_ent_sumsq[b][e];
  } else if (tid < TE + TR){
    int t = tid - TE;
    int r = r0 + t;
    sm.rsbox[t] = g_rs_box[b][r];
    sm.robox[t] = g_ro_box[b][r];
    sm.rvec[t]  = g_rel_vec[b][r];
    sm.rssq[t]  = g_rs_sumsq[b][r];
    sm.rosq[t]  = g_ro_sumsq[b][r];
  }

  // per-lane ldmatrix offsets
  int aRow = rbase + ((lane >> 3) & 1)*8 + (lane & 7);
  int aColB = (lane >> 4) * 16;                       // bytes
  uint32_t aOff = (uint32_t)aRow*SPB + aColB;
  int bRow = ebase + ((lane >> 4) & 1)*8 + (lane & 7);
  int bColB = ((lane >> 3) & 1) * 16;
  uint32_t bOff = (uint32_t)bRow*SPB + bColB;

  float accS[2][4][4], accO[2][4][4];
  #pragma unroll
  for (int mi = 0; mi < 2; mi++)
    #pragma unroll
    for (int ni = 0; ni < 4; ni++)
      #pragma unroll
      for (int q = 0; q < 4; q++){ accS[mi][ni][q] = 0.f; accO[mi][ni][q] = 0.f; }

  load_chunk(rsS, roS, entS, grs, gro, gent, 0, 0, tid);
  cp_commit();

  for (int c = 0; c < NCH; c++){
    if (c + 1 < NCH){
      load_chunk(rsS, roS, entS, grs, gro, gent, (c+1)&1, c+1, tid);
      cp_commit();
      cp_wait<1>();
    } else {
      cp_wait<0>();
    }
    __syncthreads();

    uint32_t bufo = (uint32_t)(c & 1) * BUFB;
    #pragma unroll
    for (int kk = 0; kk < 5; kk++){
      uint32_t kB = kk * 32;   // 16 bf16
      uint32_t a_rs[2][4], a_ro[2][4], bf[2][4];
      ldsm_x4(a_rs[0], rsS  + bufo + aOff + kB);
      ldsm_x4(a_rs[1], rsS  + bufo + aOff + 16*SPB + kB);
      ldsm_x4(a_ro[0], roS  + bufo + aOff + kB);
      ldsm_x4(a_ro[1], roS  + bufo + aOff + 16*SPB + kB);
      ldsm_x4(bf[0],   entS + bufo + bOff + kB);          // n8 tiles 0,1
      ldsm_x4(bf[1],   entS + bufo + bOff + 16*SPB + kB); // n8 tiles 2,3
      #pragma unroll
      for (int mi = 0; mi < 2; mi++){
        #pragma unroll
        for (int ni = 0; ni < 4; ni++){
          uint32_t b0 = bf[ni >> 1][(ni & 1)*2 + 0];
          uint32_t b1 = bf[ni >> 1][(ni & 1)*2 + 1];
          mma16816(accS[mi][ni], a_rs[mi], b0, b1);
          mma16816(accO[mi][ni], a_ro[mi], b0, b1);
        }
      }
    }
    __syncthreads();
  }

  // ---- epilogue ----
  int g = lane >> 2, t4 = lane & 3;
  #pragma unroll
  for (int mi = 0; mi < 2; mi++){
    #pragma unroll
    for (int rh = 0; rh < 2; rh++){
      int rloc = rbase + mi*16 + rh*8 + g;
      int r = r0 + rloc;
      if (r >= NR) continue;
      float4 rsb = sm.rsbox[rloc];
      float4 rob = sm.robox[rloc];
      float4 rv  = sm.rvec[rloc];
      float  sqs = sm.rssq[rloc];
      float  sqo = sm.rosq[rloc];
      float areaRS = (rsb.z - rsb.x)*(rsb.w - rsb.y);
      float areaRO = (rob.z - rob.x)*(rob.w - rob.y);
      size_t rowbase = ((size_t)b*NR + r)*NE;
      #pragma unroll
      for (int ni = 0; ni < 4; ni++){
        int eloc = ebase + ni*8 + t4*2;
        int e = e0 + eloc;
        if (e >= NE) continue;      // NE even -> pair fully valid or fully invalid
        float oS[2], oO[2];
        #pragma unroll
        for (int j = 0; j < 2; j++){
          float4 eb  = sm.ebox[eloc + j];
          float2 ec  = sm.ecnt[eloc + j];
          float  esc = sm.escore[eloc + j];
          float  eq  = sm.esq[eloc + j];
          float areaE = (eb.z - eb.x)*(eb.w - eb.y);
          float dotS = accS[mi][ni][rh*2 + j];
          float dotO = accO[mi][ni][rh*2 + j];
          // subject
          float ds  = fabsf(rv.x - ec.x) + fabsf(rv.y - ec.y);
          float ms  = esc * __fdividef(1.f, ds + 1.f);
          float d2  = sqs + eq - 2.f*dotS;
          float cd  = sqrtf(fmaxf(d2, 1e-12f));
          float cls = __fdividef(1.f, cd + 1.f);
          oS[j] = ms * cls * giou1(eb, areaE, rsb, areaRS);
          // object
          float dd   = fabsf(rv.z - ec.x) + fabsf(rv.w - ec.y);
          float mo   = esc * __fdividef(1.f, dd + 1.f);
          float d2o  = sqo + eq - 2.f*dotO;
          float cdo  = sqrtf(fmaxf(d2o, 1e-12f));
          float clso = __fdividef(1.f, cdo + 1.f);
          oO[j] = mo * clso * giou1(eb, areaE, rob, areaRO);
        }
        *(float2*)(out_s + rowbase + e) = make_float2(oS[0], oS[1]);
        *(float2*)(out_o + rowbase + e) = make_float2(oO[0], oO[1]);
      }
    }
  }
}

// ---------------- launch --------------------------------------------------------------
extern "C" void kernel_launch(void* const* d_in, const int* in_sizes, int n_in,
                              void* d_out, int out_size)
{
  const float* pred_boxes  = (const float*)d_in[0];
  const float* pred_logits = (const float*)d_in[1];
  const float* ro_logits   = (const float*)d_in[2];
  const float* rs_logits   = (const float*)d_in[3];
  const float* ro_box      = (const float*)d_in[4];
  const float* rs_box      = (const float*)d_in[5];
  const float* rel_vec     = (const float*)d_in[6];
  const float* tsizes      = (const float*)d_in[7];
  float* out_s = (float*)d_out;
  float* out_o = out_s + (size_t)BB*NR*NE;

  static bool attr_set = false;
  if (!attr_set){
    cudaFuncSetAttribute(phase2_kernel, cudaFuncAttributeMaxDynamicSharedMemorySize,
                         (int)sizeof(SmemP2));
    attr_set = true;
  }

  dim3 g1((NE + 31) / 32, BB);
  ent_kernel<<<g1, 256>>>(pred_boxes, pred_logits, tsizes);
  dim3 g2((NR + 31) / 32, BB);
  rel_kernel<<<g2, 256>>>(ro_logits, rs_logits, ro_box, rs_box, rel_vec, tsizes);
  dim3 g3(NEP / TE, NRP / TR, BB);
  phase2_kernel<<<g3, 512, sizeof(SmemP2)>>>(out_s, out_o);
}